// round 14
// baseline (speedup 1.0000x reference)
#include <cuda_runtime.h>
#include <cuda_bf16.h>
#include <cstdint>

#define BB 16
#define TT 512
#define VV 64
#define HH 64
#define BT (BB*TT)
#define VH (VV*HH)
#define TC 256

// ---------------- scratch ----------------------------------------------------
__device__ __nv_bfloat16 g_adjH[BB*4096];                  // swizzled [b][v][w]
__device__ __nv_bfloat16 g_w1H[1024];                      // swizzled [c=16][h=64]
__device__ __nv_bfloat16 g_w2H[4096];                      // swizzled [h][o]
__device__ __nv_bfloat16 g_z1b[(size_t)BT*VH];             // bf16 [bt][v][h]
__device__ __nv_bfloat16 g_z2b[(size_t)BT*VH];             // bf16 [bt][v][o]
__device__ float g_psum1[(size_t)BT*128], g_psq1[(size_t)BT*128];  // [bt][half][64]
__device__ float g_psum2[(size_t)BT*128], g_psq2[(size_t)BT*128];
__device__ float g_a1[HH], g_c1[HH], g_a2[HH], g_c2[HH];
__device__ float g_S[BB*VH], g_E0[BB*VH], g_E1[BB*VH];
__device__ float g_yp[32*256*16];                          // pool partials
__device__ float g_y[BB*TC];

extern __shared__ unsigned char s_dyn[];

// ---------------- helpers -----------------------------------------------------
__device__ __forceinline__ uint32_t toff(int r, int cB) {
    return (uint32_t)(r*128 + (cB ^ ((r & 7) << 4)));
}
__device__ __forceinline__ void ldsm4(uint32_t* r, unsigned char* p) {
    uint32_t a; asm("{ .reg .u64 t; cvta.to.shared.u64 t, %1; cvt.u32.u64 %0, t; }" : "=r"(a) : "l"(p));
    asm volatile("ldmatrix.sync.aligned.m8n8.x4.shared.b16 {%0,%1,%2,%3}, [%4];"
        : "=r"(r[0]), "=r"(r[1]), "=r"(r[2]), "=r"(r[3]) : "r"(a));
}
__device__ __forceinline__ void ldsm4t(uint32_t* r, unsigned char* p) {
    uint32_t a; asm("{ .reg .u64 t; cvta.to.shared.u64 t, %1; cvt.u32.u64 %0, t; }" : "=r"(a) : "l"(p));
    asm volatile("ldmatrix.sync.aligned.m8n8.x4.trans.shared.b16 {%0,%1,%2,%3}, [%4];"
        : "=r"(r[0]), "=r"(r[1]), "=r"(r[2]), "=r"(r[3]) : "r"(a));
}
__device__ __forceinline__ void mmabf(float* c, const uint32_t* a, uint32_t b0, uint32_t b1) {
    asm volatile("mma.sync.aligned.m16n8k16.row.col.f32.bf16.bf16.f32 "
        "{%0,%1,%2,%3},{%4,%5,%6,%7},{%8,%9},{%0,%1,%2,%3};"
        : "+f"(c[0]), "+f"(c[1]), "+f"(c[2]), "+f"(c[3])
        : "r"(a[0]), "r"(a[1]), "r"(a[2]), "r"(a[3]), "r"(b0), "r"(b1));
}
__device__ __forceinline__ uint32_t packbf(float f0, float f1) {
    uint32_t r;
    asm("cvt.rn.bf16x2.f32 %0, %1, %2;" : "=r"(r) : "f"(f1), "f"(f0));
    return r;
}
__device__ __forceinline__ uint32_t fmarelu2(uint32_t z, uint32_t a, uint32_t c) {
    uint32_t r;
    asm("fma.rn.relu.bf16x2 %0, %1, %2, %3;" : "=r"(r) : "r"(z), "r"(a), "r"(c));
    return r;
}
__device__ __forceinline__ void lda(uint32_t* a, unsigned char* base, int mt, int kt, int lane) {
    int row = mt*16 + (lane & 7) + (lane & 8);
    int cB  = kt*32 + ((lane >> 4) << 4);
    ldsm4(a, base + toff(row, cB));
}
// B fragments for TWO adjacent n-tiles via x4 trans
__device__ __forceinline__ void ldb4(uint32_t* bq, unsigned char* base, int kt, int ntp, int lane) {
    int g = lane >> 3;
    int row = kt*16 + ((g & 1) << 3) + (lane & 7);
    int cB  = ntp*32 + ((g >> 1) << 4);
    ldsm4t(bq, base + toff(row, cB));
}
#define PAIR_BAR(p) asm volatile("bar.sync %0, %1;" :: "r"((p)+1), "r"(64) : "memory")

// ---------------- K0: prep ----------------------------------------------------
__global__ void k_prep(const float* __restrict__ adj, const float* __restrict__ w1,
                       const float* __restrict__ w2) {
    int b = blockIdx.x, tid = threadIdx.x;
    __shared__ float dis[64];
    const float* A = adj + b*4096;
    if (tid < 64) {
        float s = 0.f;
        #pragma unroll 8
        for (int w = 0; w < 64; w++) s += A[tid*64 + w];
        dis[tid] = rsqrtf(s + 1e-6f);
    }
    __syncthreads();
    for (int idx = tid; idx < 4096; idx += 256) {
        int v = idx >> 6, w = idx & 63;
        float a = dis[v] * A[idx] * dis[w];
        uint32_t e = toff(v, w*2) >> 1;
        g_adjH[b*4096 + e] = __float2bfloat16(a);
    }
    if (b == 0) {
        for (int idx = tid; idx < 1024; idx += 256) {
            int c = idx >> 6, h = idx & 63;
            uint32_t e = toff(c, h*2) >> 1;
            g_w1H[e] = __float2bfloat16(w1[c*64 + h]);
        }
        for (int idx = tid; idx < 4096; idx += 256) {
            int h = idx >> 6, o = idx & 63;
            uint32_t e = toff(h, o*2) >> 1;
            g_w2H[e] = __float2bfloat16(w2[h*64 + o]);
        }
    }
}

// ---------------- half-tile epilogue: shuffle-stats + bf16 stage + store ------
__device__ __forceinline__ void epi_half(float acc[2][8][4], unsigned char* stage,
                                         int ph, int lane, __nv_bfloat16* zout,
                                         float* psum, float* psq, int bt) {
    #pragma unroll
    for (int nt = 0; nt < 8; nt++) {
        float a0=acc[0][nt][0], a1=acc[0][nt][1], a2=acc[0][nt][2], a3=acc[0][nt][3];
        float b0=acc[1][nt][0], b1=acc[1][nt][1], b2=acc[1][nt][2], b3=acc[1][nt][3];
        float p0 = a0+a2+b0+b2, p1 = a1+a3+b1+b3;
        float r0 = a0*a0+a2*a2+b0*b0+b2*b2, r1 = a1*a1+a3*a3+b1*b1+b3*b3;
        #pragma unroll
        for (int d = 4; d < 32; d <<= 1) {
            p0 += __shfl_xor_sync(0xffffffffu, p0, d);
            p1 += __shfl_xor_sync(0xffffffffu, p1, d);
            r0 += __shfl_xor_sync(0xffffffffu, r0, d);
            r1 += __shfl_xor_sync(0xffffffffu, r1, d);
        }
        if (lane < 4) {
            int c = nt*8 + lane*2;
            *(float2*)&psum[(size_t)bt*128 + ph*64 + c] = make_float2(p0, p1);
            *(float2*)&psq [(size_t)bt*128 + ph*64 + c] = make_float2(r0, r1);
        }
    }
    #pragma unroll
    for (int mt = 0; mt < 2; mt++)
        #pragma unroll
        for (int nt = 0; nt < 8; nt++) {
            int r = (2*ph + mt)*16 + (lane >> 2), cB = (nt*8 + (lane & 3)*2)*2;
            *(uint32_t*)(stage + toff(r, cB))   = packbf(acc[mt][nt][0], acc[mt][nt][1]);
            *(uint32_t*)(stage + toff(r+8, cB)) = packbf(acc[mt][nt][2], acc[mt][nt][3]);
        }
    __syncwarp();
    #pragma unroll
    for (int it = 0; it < 8; it++) {
        int idx = it*32 + lane;
        int r = 32*ph + (idx >> 3), cB = (idx & 7) * 16;
        uint4 v = *(uint4*)(stage + toff(r, cB));
        *(uint4*)((unsigned char*)zout + r*128 + cB) = v;
    }
}

// ---------------- K1: layer1 HMMA (warp-pair halves) ---------------------------
// smem: AH 0(8K) W1H 8192(2K) | pair regions 10240 + p*16384 (X at +0, tmp/stage +8192)
#define L1_PREG 10240
#define L1_SM   (10240 + 4*16384)
__global__ void __launch_bounds__(256, 2) k_l1(const float* __restrict__ x) {
    int blk = blockIdx.x, b = blk >> 7, chunk = blk & 127;
    int tid = threadIdx.x, lane = tid & 31, wq = tid >> 5;
    int p = wq >> 1, ph = wq & 1;
    unsigned char* sm = s_dyn;
    {
        const uint4* s1 = (const uint4*)(g_adjH + b*4096);
        uint4* d1 = (uint4*)sm;
        for (int i = tid; i < 512; i += 256) d1[i] = s1[i];
        const uint4* s3 = (const uint4*)g_w1H;
        uint4* d3 = (uint4*)(sm + 8192);
        if (tid < 128) d3[tid] = s3[tid];
    }
    __syncthreads();

    int t = chunk*4 + p;
    int bt = b*TT + t;
    unsigned char* XB = sm + L1_PREG + p*16384;
    unsigned char* TB = XB + 8192;
    unsigned char* AH = sm;
    unsigned char* WH = sm + 8192;

    // build X tile [w=64][c=16] bf16 (pair-split rows)
    const float* xg = x + (size_t)bt*1024;
    int tid64 = ph*32 + lane;
    #pragma unroll
    for (int it = 0; it < 4; it++) {
        int idx = it*64 + tid64;
        int r = idx >> 2, cq = (idx & 3) << 2;
        float4 u = *(const float4*)&xg[r*16 + cq];
        *(uint2*)(XB + toff(r, cq*2)) = make_uint2(packbf(u.x, u.y), packbf(u.z, u.w));
    }
    PAIR_BAR(p);

    // GEMM1': tmp[v][c] = sum_w A[v][w] X[w][c]  (warp: m-half)
    float acc1[2][2][4];
    #pragma unroll
    for (int m = 0; m < 2; m++)
        #pragma unroll
        for (int n = 0; n < 2; n++) { acc1[m][n][0]=0; acc1[m][n][1]=0; acc1[m][n][2]=0; acc1[m][n][3]=0; }
    #pragma unroll
    for (int kt = 0; kt < 4; kt++) {
        uint32_t aH[2][4], bq[4];
        lda(aH[0], AH, 2*ph,   kt, lane);
        lda(aH[1], AH, 2*ph+1, kt, lane);
        ldb4(bq, XB, kt, 0, lane);
        #pragma unroll
        for (int mt = 0; mt < 2; mt++) {
            mmabf(acc1[mt][0], aH[mt], bq[0], bq[1]);
            mmabf(acc1[mt][1], aH[mt], bq[2], bq[3]);
        }
    }
    __syncwarp();
    // stage tmp (own rows) to TB
    #pragma unroll
    for (int mt = 0; mt < 2; mt++)
        #pragma unroll
        for (int nt = 0; nt < 2; nt++) {
            int r = (2*ph + mt)*16 + (lane >> 2), cB = (nt*8 + (lane & 3)*2)*2;
            *(uint32_t*)(TB + toff(r, cB))   = packbf(acc1[mt][nt][0], acc1[mt][nt][1]);
            *(uint32_t*)(TB + toff(r+8, cB)) = packbf(acc1[mt][nt][2], acc1[mt][nt][3]);
        }
    __syncwarp();

    // GEMM2': z1[v][h] = sum_c tmp[v][c] W1[c][h]  (A rows warp-local)
    float acc2[2][8][4];
    #pragma unroll
    for (int m = 0; m < 2; m++)
        #pragma unroll
        for (int n = 0; n < 8; n++) { acc2[m][n][0]=0; acc2[m][n][1]=0; acc2[m][n][2]=0; acc2[m][n][3]=0; }
    {
        uint32_t aH[2][4];
        lda(aH[0], TB, 2*ph,   0, lane);
        lda(aH[1], TB, 2*ph+1, 0, lane);
        #pragma unroll
        for (int ntp = 0; ntp < 4; ntp++) {
            uint32_t bq[4];
            ldb4(bq, WH, 0, ntp, lane);
            #pragma unroll
            for (int mt = 0; mt < 2; mt++) {
                mmabf(acc2[mt][2*ntp],   aH[mt], bq[0], bq[1]);
                mmabf(acc2[mt][2*ntp+1], aH[mt], bq[2], bq[3]);
            }
        }
    }
    __syncwarp();
    epi_half(acc2, TB, ph, lane, g_z1b + (size_t)bt*4096, g_psum1, g_psq1, bt);
}

// ---------------- K2: finalize BN affine ---------------------------------------
__global__ void k_stats(int layer, const float* __restrict__ g, const float* __restrict__ be) {
    int h = blockIdx.x, tid = threadIdx.x;
    const float* ps = layer ? g_psum2 : g_psum1;
    const float* pq = layer ? g_psq2  : g_psq1;
    __shared__ float ss[256], sq[256];
    float s = 0.f, q = 0.f;
    for (int i = tid; i < BT; i += 256) {
        s += ps[(size_t)i*128 + h] + ps[(size_t)i*128 + 64 + h];
        q += pq[(size_t)i*128 + h] + pq[(size_t)i*128 + 64 + h];
    }
    ss[tid] = s; sq[tid] = q;
    __syncthreads();
    for (int st = 128; st > 0; st >>= 1) {
        if (tid < st) { ss[tid] += ss[tid+st]; sq[tid] += sq[tid+st]; }
        __syncthreads();
    }
    if (tid == 0) {
        const float N = (float)(BT*VV);
        float mean = ss[0] / N;
        float var  = sq[0] / N - mean*mean;
        float av = g[h] * rsqrtf(var + 1e-5f);
        if (layer) { g_a2[h] = av; g_c2[h] = be[h] - mean*av; }
        else       { g_a1[h] = av; g_c1[h] = be[h] - mean*av; }
    }
}

// ---------------- K3: layer2 HMMA (warp-pair halves) ---------------------------
// smem: AH 0(8K) W2H 8192(8K) a1p/c1p 16384(256B) | pair regions 16640 + p*16384
#define L2_PREG 16640
#define L2_SM   (16640 + 4*16384)
__global__ void __launch_bounds__(256, 2) k_l2() {
    int blk = blockIdx.x, b = blk >> 7, chunk = blk & 127;
    int tid = threadIdx.x, lane = tid & 31, wq = tid >> 5;
    int p = wq >> 1, ph = wq & 1;
    unsigned char* sm = s_dyn;
    uint32_t* a1p = (uint32_t*)(sm + 16384);
    uint32_t* c1p = a1p + 32;
    {
        const uint4* s1 = (const uint4*)(g_adjH + b*4096);
        uint4* d1 = (uint4*)sm;
        for (int i = tid; i < 512; i += 256) d1[i] = s1[i];
        const uint4* s3 = (const uint4*)g_w2H;
        uint4* d3 = (uint4*)(sm + 8192);
        for (int i = tid; i < 512; i += 256) d3[i] = s3[i];
        if (tid < 32) {
            a1p[tid] = packbf(g_a1[2*tid], g_a1[2*tid+1]);
            c1p[tid] = packbf(g_c1[2*tid], g_c1[2*tid+1]);
        }
    }
    __syncthreads();

    int t = chunk*4 + p;
    int bt = b*TT + t;
    unsigned char* XB = sm + L2_PREG + p*16384;   // x1
    unsigned char* TB = XB + 8192;                 // tmp + epilogue stage
    unsigned char* AH = sm;
    unsigned char* WH = sm + 8192;

    // build x1 tile [w=64][h=64] = relu(a1*z1+c1), pair-split rows
    const unsigned char* ztb = (const unsigned char*)(g_z1b + (size_t)bt*4096);
    int tid64 = ph*32 + lane;
    #pragma unroll
    for (int it = 0; it < 16; it++) {
        int idx = it*64 + tid64;
        int r = idx >> 4, cq = (idx & 15) << 2;
        uint2 u = *(const uint2*)(ztb + (r*64 + cq)*2);
        uint32_t v0 = fmarelu2(u.x, a1p[cq >> 1],       c1p[cq >> 1]);
        uint32_t v1 = fmarelu2(u.y, a1p[(cq >> 1) + 1], c1p[(cq >> 1) + 1]);
        *(uint2*)(XB + toff(r, cq*2)) = make_uint2(v0, v1);
    }
    PAIR_BAR(p);

    float acc[2][8][4];
    #pragma unroll
    for (int m = 0; m < 2; m++)
        #pragma unroll
        for (int n = 0; n < 8; n++) { acc[m][n][0]=0; acc[m][n][1]=0; acc[m][n][2]=0; acc[m][n][3]=0; }

    // GEMM1: tmp[v][h] = sum_w A[v][w] x1[w][h]  (warp: m-half)
    #pragma unroll
    for (int kt = 0; kt < 4; kt++) {
        uint32_t aH[2][4];
        lda(aH[0], AH, 2*ph,   kt, lane);
        lda(aH[1], AH, 2*ph+1, kt, lane);
        #pragma unroll
        for (int ntp = 0; ntp < 4; ntp++) {
            uint32_t bq[4];
            ldb4(bq, XB, kt, ntp, lane);
            #pragma unroll
            for (int mt = 0; mt < 2; mt++) {
                mmabf(acc[mt][2*ntp],   aH[mt], bq[0], bq[1]);
                mmabf(acc[mt][2*ntp+1], aH[mt], bq[2], bq[3]);
            }
        }
    }
    __syncwarp();
    // stage tmp (own rows) to TB
    #pragma unroll
    for (int mt = 0; mt < 2; mt++)
        #pragma unroll
        for (int nt = 0; nt < 8; nt++) {
            int r = (2*ph + mt)*16 + (lane >> 2), cB = (nt*8 + (lane & 3)*2)*2;
            *(uint32_t*)(TB + toff(r, cB))   = packbf(acc[mt][nt][0], acc[mt][nt][1]);
            *(uint32_t*)(TB + toff(r+8, cB)) = packbf(acc[mt][nt][2], acc[mt][nt][3]);
        }
    __syncwarp();

    // GEMM2: z2[v][o] = sum_h tmp[v][h] W2[h][o]  (A rows warp-local)
    #pragma unroll
    for (int m = 0; m < 2; m++)
        #pragma unroll
        for (int n = 0; n < 8; n++) { acc[m][n][0]=0; acc[m][n][1]=0; acc[m][n][2]=0; acc[m][n][3]=0; }
    #pragma unroll
    for (int kt = 0; kt < 4; kt++) {
        uint32_t aH[2][4];
        lda(aH[0], TB, 2*ph,   kt, lane);
        lda(aH[1], TB, 2*ph+1, kt, lane);
        #pragma unroll
        for (int ntp = 0; ntp < 4; ntp++) {
            uint32_t bq[4];
            ldb4(bq, WH, kt, ntp, lane);
            #pragma unroll
            for (int mt = 0; mt < 2; mt++) {
                mmabf(acc[mt][2*ntp],   aH[mt], bq[0], bq[1]);
                mmabf(acc[mt][2*ntp+1], aH[mt], bq[2], bq[3]);
            }
        }
    }
    __syncwarp();
    epi_half(acc, TB, ph, lane, g_z2b + (size_t)bt*4096, g_psum2, g_psq2, bt);
}

// ---------------- K4: S = sum_t [relu(BN1(z1)) + relu(BN2(z2))]; edges ---------
__global__ void __launch_bounds__(256) k_sumfinal() {
    int bv = blockIdx.x, b = bv >> 6, v = bv & 63;
    int tid = threadIdx.x;
    int hq = (tid & 15) << 2, ph = tid >> 4;
    float4 A1 = *(float4*)&g_a1[hq], C1 = *(float4*)&g_c1[hq];
    float4 A2 = *(float4*)&g_a2[hq], C2 = *(float4*)&g_c2[hq];
    float4 s = make_float4(0.f,0.f,0.f,0.f);
    float4 e0 = s, e1 = s;
    #pragma unroll 4
    for (int t = ph; t < TT; t += 16) {
        size_t i1 = (((size_t)(b*TT + t))*64 + v)*64 + hq;
        uint2 u1 = *(const uint2*)&g_z1b[i1];
        uint2 u2 = *(const uint2*)&g_z2b[i1];
        float x0 = fmaxf(fmaf(__uint_as_float(u1.x << 16),         A1.x, C1.x), 0.f)
                 + fmaxf(fmaf(__uint_as_float(u2.x << 16),         A2.x, C2.x), 0.f);
        float x1 = fmaxf(fmaf(__uint_as_float(u1.x & 0xffff0000u), A1.y, C1.y), 0.f)
                 + fmaxf(fmaf(__uint_as_float(u2.x & 0xffff0000u), A2.y, C2.y), 0.f);
        float x2 = fmaxf(fmaf(__uint_as_float(u1.y << 16),         A1.z, C1.z), 0.f)
                 + fmaxf(fmaf(__uint_as_float(u2.y << 16),         A2.z, C2.z), 0.f);
        float x3 = fmaxf(fmaf(__uint_as_float(u1.y & 0xffff0000u), A1.w, C1.w), 0.f)
                 + fmaxf(fmaf(__uint_as_float(u2.y & 0xffff0000u), A2.w, C2.w), 0.f);
        s.x += x0; s.y += x1; s.z += x2; s.w += x3;
        if (t == 0)    e0 = make_float4(x0, x1, x2, x3);
        if (t == TT-1) e1 = make_float4(x0, x1, x2, x3);
    }
    __shared__ float sr[16][64], se0[64], se1[64];
    *(float4*)&sr[ph][hq] = s;
    if (ph == 0)  *(float4*)&se0[hq] = e0;
    if (ph == 15) *(float4*)&se1[hq] = e1;
    __syncthreads();
    if (tid < 64) {
        float S = 0.f;
        #pragma unroll
        for (int p = 0; p < 16; p++) S += sr[p][tid];
        int o = b*4096 + v*64 + tid;
        g_S[o]  = S;
        g_E0[o] = se0[tid];
        g_E1[o] = se1[tid];
    }
}

// ---------------- K5a: pool partials (i-tiles x o-tiles) ----------------------
__global__ void __launch_bounds__(256) k_poolA(const float* __restrict__ tw) {
    int itile = blockIdx.x;   // 0..31
    int otile = blockIdx.y;   // 0..15
    int tid = threadIdx.x, lane = tid & 31, wq = tid >> 5;
    __shared__ float sS[16][128], sE0[16][128], sE1[16][128];
    int i0 = itile*128;
    #pragma unroll
    for (int k = 0; k < 2; k++) {
        int i4 = k*256 + tid;
        int b = i4 >> 5, ii = (i4 & 31) << 2;
        *(float4*)&sS[b][ii]  = *(const float4*)&g_S [b*4096 + i0 + ii];
        *(float4*)&sE0[b][ii] = *(const float4*)&g_E0[b*4096 + i0 + ii];
        *(float4*)&sE1[b][ii] = *(const float4*)&g_E1[b*4096 + i0 + ii];
    }
    __syncthreads();
    #pragma unroll
    for (int pass = 0; pass < 2; pass++) {
        int o = otile*16 + pass*8 + wq;
        float acc[16];
        #pragma unroll
        for (int b = 0; b < 16; b++) acc[b] = 0.f;
        #pragma unroll
        for (int k = 0; k < 4; k++) {
            int i = k*32 + lane;
            const float* twp = tw + ((size_t)o*4096 + i0 + i)*3;
            float t0 = twp[0], t1 = twp[1], t2 = twp[2];
            float ts = t0 + t1 + t2;
            #pragma unroll
            for (int b = 0; b < 16; b++)
                acc[b] += ts*sS[b][i] - t0*sE1[b][i] - t2*sE0[b][i];
        }
        float mine = 0.f;
        #pragma unroll
        for (int b = 0; b < 16; b++) {
            float v = acc[b];
            #pragma unroll
            for (int d = 16; d > 0; d >>= 1) v += __shfl_xor_sync(0xffffffffu, v, d);
            if (lane == b) mine = v;
        }
        if (lane < 16) g_yp[((size_t)itile*256 + o)*16 + lane] = mine;
    }
}

// ---------------- K5b: reduce pool partials ------------------------------------
__global__ void __launch_bounds__(256) k_poolB(const float* __restrict__ tb) {
    int tid = threadIdx.x;
    int o = blockIdx.x*16 + (tid >> 4);
    int b = tid & 15;
    float s = 0.f;
    #pragma unroll 8
    for (int it = 0; it < 32; it++) s += g_yp[((size_t)it*256 + o)*16 + b];
    g_y[b*TC + o] = s*(1.f/TT) + tb[o];
}

// ---------------- K6: FC head ---------------------------------------------------
__global__ void __launch_bounds__(256) k_fc(const float* __restrict__ f1w,
                                            const float* __restrict__ f1b,
                                            const float* __restrict__ f2w,
                                            const float* __restrict__ f2b,
                                            float* __restrict__ out) {
    __shared__ float ys[BB*TC];
    __shared__ float hs[BB*128];
    int tid = threadIdx.x;
    for (int i = tid; i < BB*TC; i += 256) ys[i] = g_y[i];
    __syncthreads();
    int b = tid >> 4, jq = (tid & 15) * 8;
    float acc[8];
    #pragma unroll
    for (int j = 0; j < 8; j++) acc[j] = f1b[jq+j];
    for (int o = 0; o < TC; o++) {
        float yv = ys[b*TC + o];
        const float* w = f1w + o*128 + jq;
        #pragma unroll
        for (int j = 0; j < 8; j++) acc[j] += yv * w[j];
    }
    #pragma unroll
    for (int j = 0; j < 8; j++) hs[b*128 + jq + j] = fmaxf(acc[j], 0.f);
    __syncthreads();
    if (tid < BB*10) {
        int bb = tid / 10, n = tid % 10;
        float s = f2b[n];
        #pragma unroll 8
        for (int j = 0; j < 128; j++) s += hs[bb*128 + j] * f2w[j*10 + n];
        out[tid] = s;
    }
}

// ---------------- launch ---------------------------------------------------------
extern "C" void kernel_launch(void* const* d_in, const int* in_sizes, int n_in,
                              void* d_out, int out_size) {
    const float* x    = (const float*)d_in[0];
    const float* adj  = (const float*)d_in[1];
    const float* w1   = (const float*)d_in[2];
    const float* g1   = (const float*)d_in[4];
    const float* be1  = (const float*)d_in[5];
    const float* w2   = (const float*)d_in[6];
    const float* g2   = (const float*)d_in[8];
    const float* be2  = (const float*)d_in[9];
    const float* tw   = (const float*)d_in[10];
    const float* tb   = (const float*)d_in[11];
    const float* f1w  = (const float*)d_in[12];
    const float* f1b  = (const float*)d_in[13];
    const float* f2w  = (const float*)d_in[14];
    const float* f2b  = (const float*)d_in[15];
    float* out = (float*)d_out;

    cudaFuncSetAttribute(k_l1, cudaFuncAttributeMaxDynamicSharedMemorySize, L1_SM);
    cudaFuncSetAttribute(k_l2, cudaFuncAttributeMaxDynamicSharedMemorySize, L2_SM);

    k_prep<<<BB, 256>>>(adj, w1, w2);
    k_l1<<<BB*128, 256, L1_SM>>>(x);
    k_stats<<<HH, 256>>>(0, g1, be1);
    k_l2<<<BB*128, 256, L2_SM>>>();
    k_stats<<<HH, 256>>>(1, g2, be2);
    k_sumfinal<<<BB*VV, 256>>>();
    dim3 gp(32, 16);
    k_poolA<<<gp, 256>>>(tw);
    k_poolB<<<16, 256>>>(tb);
    k_fc<<<1, 256>>>(f1w, f1b, f2w, f2b, out);
}

// round 15
// speedup vs baseline: 1.0447x; 1.0447x over previous
#include <cuda_runtime.h>
#include <cuda_bf16.h>
#include <cstdint>

#define BB 16
#define TT 512
#define VV 64
#define HH 64
#define BT (BB*TT)
#define VH (VV*HH)
#define TC 256

// ---------------- scratch ----------------------------------------------------
__device__ __nv_bfloat16 g_adjH[BB*4096];                  // swizzled [b][v][w]
__device__ __nv_bfloat16 g_w1H[1024];                      // swizzled [c=16][h=64]
__device__ __nv_bfloat16 g_w2H[4096];                      // swizzled [h][o]
__device__ __nv_bfloat16 g_z1b[(size_t)BT*VH];             // bf16 [bt][v][h]
__device__ __nv_bfloat16 g_z2b[(size_t)BT*VH];             // bf16 [bt][v][o]
__device__ float g_psum1[(size_t)BT*64],  g_psq1[(size_t)BT*64];   // [bt][64]
__device__ float g_psum2[(size_t)BT*128], g_psq2[(size_t)BT*128];  // [bt][half][64]
__device__ float g_a1[HH], g_c1[HH], g_a2[HH], g_c2[HH];
__device__ float g_S[BB*VH], g_E0[BB*VH], g_E1[BB*VH];
__device__ float g_yp[32*256*16];                          // pool partials
__device__ float g_y[BB*TC];

extern __shared__ unsigned char s_dyn[];

// ---------------- helpers -----------------------------------------------------
__device__ __forceinline__ uint32_t toff(int r, int cB) {
    return (uint32_t)(r*128 + (cB ^ ((r & 7) << 4)));
}
__device__ __forceinline__ void ldsm4(uint32_t* r, unsigned char* p) {
    uint32_t a; asm("{ .reg .u64 t; cvta.to.shared.u64 t, %1; cvt.u32.u64 %0, t; }" : "=r"(a) : "l"(p));
    asm volatile("ldmatrix.sync.aligned.m8n8.x4.shared.b16 {%0,%1,%2,%3}, [%4];"
        : "=r"(r[0]), "=r"(r[1]), "=r"(r[2]), "=r"(r[3]) : "r"(a));
}
__device__ __forceinline__ void ldsm4t(uint32_t* r, unsigned char* p) {
    uint32_t a; asm("{ .reg .u64 t; cvta.to.shared.u64 t, %1; cvt.u32.u64 %0, t; }" : "=r"(a) : "l"(p));
    asm volatile("ldmatrix.sync.aligned.m8n8.x4.trans.shared.b16 {%0,%1,%2,%3}, [%4];"
        : "=r"(r[0]), "=r"(r[1]), "=r"(r[2]), "=r"(r[3]) : "r"(a));
}
__device__ __forceinline__ void mmabf(float* c, const uint32_t* a, uint32_t b0, uint32_t b1) {
    asm volatile("mma.sync.aligned.m16n8k16.row.col.f32.bf16.bf16.f32 "
        "{%0,%1,%2,%3},{%4,%5,%6,%7},{%8,%9},{%0,%1,%2,%3};"
        : "+f"(c[0]), "+f"(c[1]), "+f"(c[2]), "+f"(c[3])
        : "r"(a[0]), "r"(a[1]), "r"(a[2]), "r"(a[3]), "r"(b0), "r"(b1));
}
__device__ __forceinline__ uint32_t packbf(float f0, float f1) {
    uint32_t r;
    asm("cvt.rn.bf16x2.f32 %0, %1, %2;" : "=r"(r) : "f"(f1), "f"(f0));
    return r;
}
__device__ __forceinline__ uint32_t fmarelu2(uint32_t z, uint32_t a, uint32_t c) {
    uint32_t r;
    asm("fma.rn.relu.bf16x2 %0, %1, %2, %3;" : "=r"(r) : "r"(z), "r"(a), "r"(c));
    return r;
}
__device__ __forceinline__ void lda(uint32_t* a, unsigned char* base, int mt, int kt, int lane) {
    int row = mt*16 + (lane & 7) + (lane & 8);
    int cB  = kt*32 + ((lane >> 4) << 4);
    ldsm4(a, base + toff(row, cB));
}
// B fragments for TWO adjacent n-tiles via x4 trans
__device__ __forceinline__ void ldb4(uint32_t* bq, unsigned char* base, int kt, int ntp, int lane) {
    int g = lane >> 3;
    int row = kt*16 + ((g & 1) << 3) + (lane & 7);
    int cB  = ntp*32 + ((g >> 1) << 4);
    ldsm4t(bq, base + toff(row, cB));
}
#define PAIR_BAR(p) asm volatile("bar.sync %0, %1;" :: "r"((p)+1), "r"(64) : "memory")

// ---------------- K0: prep ----------------------------------------------------
__global__ void k_prep(const float* __restrict__ adj, const float* __restrict__ w1,
                       const float* __restrict__ w2) {
    int b = blockIdx.x, tid = threadIdx.x;
    __shared__ float dis[64];
    const float* A = adj + b*4096;
    if (tid < 64) {
        float s = 0.f;
        #pragma unroll 8
        for (int w = 0; w < 64; w++) s += A[tid*64 + w];
        dis[tid] = rsqrtf(s + 1e-6f);
    }
    __syncthreads();
    for (int idx = tid; idx < 4096; idx += 256) {
        int v = idx >> 6, w = idx & 63;
        float a = dis[v] * A[idx] * dis[w];
        uint32_t e = toff(v, w*2) >> 1;
        g_adjH[b*4096 + e] = __float2bfloat16(a);
    }
    if (b == 0) {
        for (int idx = tid; idx < 1024; idx += 256) {
            int c = idx >> 6, h = idx & 63;
            uint32_t e = toff(c, h*2) >> 1;
            g_w1H[e] = __float2bfloat16(w1[c*64 + h]);
        }
        for (int idx = tid; idx < 4096; idx += 256) {
            int h = idx >> 6, o = idx & 63;
            uint32_t e = toff(h, o*2) >> 1;
            g_w2H[e] = __float2bfloat16(w2[h*64 + o]);
        }
    }
}

// ---------------- full-tile epilogue (k_l1): shuffle-stats + bf16 store --------
__device__ __forceinline__ void epilogue_reg(float acc[4][8][4], unsigned char* stage, int lane,
                                             __nv_bfloat16* zout, float* psum, float* psq, int bt) {
    #pragma unroll
    for (int nt = 0; nt < 8; nt++) {
        float p0=0.f, p1=0.f, r0=0.f, r1=0.f;
        #pragma unroll
        for (int mt = 0; mt < 4; mt++) {
            float a0=acc[mt][nt][0], a1=acc[mt][nt][1], a2=acc[mt][nt][2], a3=acc[mt][nt][3];
            p0 += a0 + a2; p1 += a1 + a3;
            r0 += a0*a0 + a2*a2; r1 += a1*a1 + a3*a3;
        }
        #pragma unroll
        for (int d = 4; d < 32; d <<= 1) {
            p0 += __shfl_xor_sync(0xffffffffu, p0, d);
            p1 += __shfl_xor_sync(0xffffffffu, p1, d);
            r0 += __shfl_xor_sync(0xffffffffu, r0, d);
            r1 += __shfl_xor_sync(0xffffffffu, r1, d);
        }
        if (lane < 4) {
            int c = nt*8 + lane*2;
            *(float2*)&psum[(size_t)bt*64 + c] = make_float2(p0, p1);
            *(float2*)&psq [(size_t)bt*64 + c] = make_float2(r0, r1);
        }
    }
    #pragma unroll
    for (int mt = 0; mt < 4; mt++)
        #pragma unroll
        for (int nt = 0; nt < 8; nt++) {
            int r = mt*16 + (lane >> 2), cB = (nt*8 + (lane & 3)*2)*2;
            *(uint32_t*)(stage + toff(r, cB))   = packbf(acc[mt][nt][0], acc[mt][nt][1]);
            *(uint32_t*)(stage + toff(r+8, cB)) = packbf(acc[mt][nt][2], acc[mt][nt][3]);
        }
    __syncwarp();
    #pragma unroll
    for (int it = 0; it < 16; it++) {
        int idx = it*32 + lane;
        int r = idx >> 3, cB = (idx & 7) * 16;
        uint4 v = *(uint4*)(stage + toff(r, cB));
        *(uint4*)((unsigned char*)zout + r*128 + cB) = v;
    }
}

// ---------------- half-tile epilogue (k_l2) ------------------------------------
__device__ __forceinline__ void epi_half(float acc[2][8][4], unsigned char* stage,
                                         int ph, int lane, __nv_bfloat16* zout,
                                         float* psum, float* psq, int bt) {
    #pragma unroll
    for (int nt = 0; nt < 8; nt++) {
        float a0=acc[0][nt][0], a1=acc[0][nt][1], a2=acc[0][nt][2], a3=acc[0][nt][3];
        float b0=acc[1][nt][0], b1=acc[1][nt][1], b2=acc[1][nt][2], b3=acc[1][nt][3];
        float p0 = a0+a2+b0+b2, p1 = a1+a3+b1+b3;
        float r0 = a0*a0+a2*a2+b0*b0+b2*b2, r1 = a1*a1+a3*a3+b1*b1+b3*b3;
        #pragma unroll
        for (int d = 4; d < 32; d <<= 1) {
            p0 += __shfl_xor_sync(0xffffffffu, p0, d);
            p1 += __shfl_xor_sync(0xffffffffu, p1, d);
            r0 += __shfl_xor_sync(0xffffffffu, r0, d);
            r1 += __shfl_xor_sync(0xffffffffu, r1, d);
        }
        if (lane < 4) {
            int c = nt*8 + lane*2;
            *(float2*)&psum[(size_t)bt*128 + ph*64 + c] = make_float2(p0, p1);
            *(float2*)&psq [(size_t)bt*128 + ph*64 + c] = make_float2(r0, r1);
        }
    }
    #pragma unroll
    for (int mt = 0; mt < 2; mt++)
        #pragma unroll
        for (int nt = 0; nt < 8; nt++) {
            int r = (2*ph + mt)*16 + (lane >> 2), cB = (nt*8 + (lane & 3)*2)*2;
            *(uint32_t*)(stage + toff(r, cB))   = packbf(acc[mt][nt][0], acc[mt][nt][1]);
            *(uint32_t*)(stage + toff(r+8, cB)) = packbf(acc[mt][nt][2], acc[mt][nt][3]);
        }
    __syncwarp();
    #pragma unroll
    for (int it = 0; it < 8; it++) {
        int idx = it*32 + lane;
        int r = 32*ph + (idx >> 3), cB = (idx & 7) * 16;
        uint4 v = *(uint4*)(stage + toff(r, cB));
        *(uint4*)((unsigned char*)zout + r*128 + cB) = v;
    }
}

// ---------------- K1: layer1 HMMA (single-warp tiles, round-13 form) -----------
// smem: AH 0(8K) W1H 8192(2K) | wreg 10240 + wq*8192
#define L1_WREG 10240
#define L1_SM   (10240 + 4*8192)
__global__ void __launch_bounds__(128, 3) k_l1(const float* __restrict__ x) {
    int blk = blockIdx.x, b = blk >> 7, chunk = blk & 127;
    int tid = threadIdx.x, lane = tid & 31, wq = tid >> 5;
    unsigned char* sm = s_dyn;
    {
        const uint4* s1 = (const uint4*)(g_adjH + b*4096);
        uint4* d1 = (uint4*)sm;
        for (int i = tid; i < 512; i += 128) d1[i] = s1[i];
        const uint4* s3 = (const uint4*)g_w1H;
        uint4* d3 = (uint4*)(sm + 8192);
        if (tid < 128) d3[tid] = s3[tid];
    }
    __syncthreads();

    int t = chunk*4 + wq;
    int bt = b*TT + t;
    unsigned char* XH = sm + L1_WREG + wq*8192;
    unsigned char* AH = sm;
    unsigned char* WH = sm + 8192;

    // build X tile [w=64][c=16] bf16 hi
    const float* xg = x + (size_t)bt*1024;
    #pragma unroll
    for (int it = 0; it < 8; it++) {
        int idx = it*32 + lane;
        int r = idx >> 2, cq = (idx & 3) << 2;
        float4 u = *(const float4*)&xg[r*16 + cq];
        *(uint2*)(XH + toff(r, cq*2)) = make_uint2(packbf(u.x, u.y), packbf(u.z, u.w));
    }
    __syncwarp();

    // GEMM1': tmp[v][c] = sum_w A[v][w] X[w][c]  (1-term)
    float acc1[4][2][4];
    #pragma unroll
    for (int m = 0; m < 4; m++)
        #pragma unroll
        for (int n = 0; n < 2; n++) { acc1[m][n][0]=0; acc1[m][n][1]=0; acc1[m][n][2]=0; acc1[m][n][3]=0; }
    #pragma unroll
    for (int kt = 0; kt < 4; kt++) {
        uint32_t aH[4][4], bq[4];
        #pragma unroll
        for (int mt = 0; mt < 4; mt++) lda(aH[mt], AH, mt, kt, lane);
        ldb4(bq, XH, kt, 0, lane);
        #pragma unroll
        for (int mt = 0; mt < 4; mt++) {
            mmabf(acc1[mt][0], aH[mt], bq[0], bq[1]);
            mmabf(acc1[mt][1], aH[mt], bq[2], bq[3]);
        }
    }
    __syncwarp();
    #pragma unroll
    for (int mt = 0; mt < 4; mt++)
        #pragma unroll
        for (int nt = 0; nt < 2; nt++) {
            int r = mt*16 + (lane >> 2), cB = (nt*8 + (lane & 3)*2)*2;
            *(uint32_t*)(XH + toff(r, cB))   = packbf(acc1[mt][nt][0], acc1[mt][nt][1]);
            *(uint32_t*)(XH + toff(r+8, cB)) = packbf(acc1[mt][nt][2], acc1[mt][nt][3]);
        }
    __syncwarp();

    // GEMM2': z1[v][h] = sum_c tmp[v][c] W1[c][h]  (1-term)
    float acc2[4][8][4];
    #pragma unroll
    for (int m = 0; m < 4; m++)
        #pragma unroll
        for (int n = 0; n < 8; n++) { acc2[m][n][0]=0; acc2[m][n][1]=0; acc2[m][n][2]=0; acc2[m][n][3]=0; }
    {
        uint32_t aH[4][4];
        #pragma unroll
        for (int mt = 0; mt < 4; mt++) lda(aH[mt], XH, mt, 0, lane);
        #pragma unroll
        for (int ntp = 0; ntp < 4; ntp++) {
            uint32_t bq[4];
            ldb4(bq, WH, 0, ntp, lane);
            #pragma unroll
            for (int mt = 0; mt < 4; mt++) {
                mmabf(acc2[mt][2*ntp],   aH[mt], bq[0], bq[1]);
                mmabf(acc2[mt][2*ntp+1], aH[mt], bq[2], bq[3]);
            }
        }
    }
    __syncwarp();
    epilogue_reg(acc2, XH, lane, g_z1b + (size_t)bt*4096, g_psum1, g_psq1, bt);
}

// ---------------- K2: finalize BN affine ---------------------------------------
__global__ void k_stats(int layer, const float* __restrict__ g, const float* __restrict__ be) {
    int h = blockIdx.x, tid = threadIdx.x;
    __shared__ float ss[256], sq[256];
    float s = 0.f, q = 0.f;
    if (layer == 0) {
        for (int i = tid; i < BT; i += 256) {
            s += g_psum1[(size_t)i*64 + h];
            q += g_psq1 [(size_t)i*64 + h];
        }
    } else {
        for (int i = tid; i < BT; i += 256) {
            s += g_psum2[(size_t)i*128 + h] + g_psum2[(size_t)i*128 + 64 + h];
            q += g_psq2 [(size_t)i*128 + h] + g_psq2 [(size_t)i*128 + 64 + h];
        }
    }
    ss[tid] = s; sq[tid] = q;
    __syncthreads();
    for (int st = 128; st > 0; st >>= 1) {
        if (tid < st) { ss[tid] += ss[tid+st]; sq[tid] += sq[tid+st]; }
        __syncthreads();
    }
    if (tid == 0) {
        const float N = (float)(BT*VV);
        float mean = ss[0] / N;
        float var  = sq[0] / N - mean*mean;
        float av = g[h] * rsqrtf(var + 1e-5f);
        if (layer) { g_a2[h] = av; g_c2[h] = be[h] - mean*av; }
        else       { g_a1[h] = av; g_c1[h] = be[h] - mean*av; }
    }
}

// ---------------- K3: layer2 HMMA (warp-pair halves, round-14 form) ------------
// smem: AH 0(8K) W2H 8192(8K) a1p/c1p 16384(256B) | pair regions 16640 + p*16384
#define L2_PREG 16640
#define L2_SM   (16640 + 4*16384)
__global__ void __launch_bounds__(256, 2) k_l2() {
    int blk = blockIdx.x, b = blk >> 7, chunk = blk & 127;
    int tid = threadIdx.x, lane = tid & 31, wq = tid >> 5;
    int p = wq >> 1, ph = wq & 1;
    unsigned char* sm = s_dyn;
    uint32_t* a1p = (uint32_t*)(sm + 16384);
    uint32_t* c1p = a1p + 32;
    {
        const uint4* s1 = (const uint4*)(g_adjH + b*4096);
        uint4* d1 = (uint4*)sm;
        for (int i = tid; i < 512; i += 256) d1[i] = s1[i];
        const uint4* s3 = (const uint4*)g_w2H;
        uint4* d3 = (uint4*)(sm + 8192);
        for (int i = tid; i < 512; i += 256) d3[i] = s3[i];
        if (tid < 32) {
            a1p[tid] = packbf(g_a1[2*tid], g_a1[2*tid+1]);
            c1p[tid] = packbf(g_c1[2*tid], g_c1[2*tid+1]);
        }
    }
    __syncthreads();

    int t = chunk*4 + p;
    int bt = b*TT + t;
    unsigned char* XB = sm + L2_PREG + p*16384;   // x1
    unsigned char* TB = XB + 8192;                 // tmp + epilogue stage
    unsigned char* AH = sm;
    unsigned char* WH = sm + 8192;

    // build x1 tile [w=64][h=64] = relu(a1*z1+c1), pair-split rows
    const unsigned char* ztb = (const unsigned char*)(g_z1b + (size_t)bt*4096);
    int tid64 = ph*32 + lane;
    #pragma unroll
    for (int it = 0; it < 16; it++) {
        int idx = it*64 + tid64;
        int r = idx >> 4, cq = (idx & 15) << 2;
        uint2 u = *(const uint2*)(ztb + (r*64 + cq)*2);
        uint32_t v0 = fmarelu2(u.x, a1p[cq >> 1],       c1p[cq >> 1]);
        uint32_t v1 = fmarelu2(u.y, a1p[(cq >> 1) + 1], c1p[(cq >> 1) + 1]);
        *(uint2*)(XB + toff(r, cq*2)) = make_uint2(v0, v1);
    }
    PAIR_BAR(p);

    float acc[2][8][4];
    #pragma unroll
    for (int m = 0; m < 2; m++)
        #pragma unroll
        for (int n = 0; n < 8; n++) { acc[m][n][0]=0; acc[m][n][1]=0; acc[m][n][2]=0; acc[m][n][3]=0; }

    // GEMM1: tmp[v][h] = sum_w A[v][w] x1[w][h]  (warp: m-half)
    #pragma unroll
    for (int kt = 0; kt < 4; kt++) {
        uint32_t aH[2][4];
        lda(aH[0], AH, 2*ph,   kt, lane);
        lda(aH[1], AH, 2*ph+1, kt, lane);
        #pragma unroll
        for (int ntp = 0; ntp < 4; ntp++) {
            uint32_t bq[4];
            ldb4(bq, XB, kt, ntp, lane);
            #pragma unroll
            for (int mt = 0; mt < 2; mt++) {
                mmabf(acc[mt][2*ntp],   aH[mt], bq[0], bq[1]);
                mmabf(acc[mt][2*ntp+1], aH[mt], bq[2], bq[3]);
            }
        }
    }
    __syncwarp();
    // stage tmp (own rows) to TB
    #pragma unroll
    for (int mt = 0; mt < 2; mt++)
        #pragma unroll
        for (int nt = 0; nt < 8; nt++) {
            int r = (2*ph + mt)*16 + (lane >> 2), cB = (nt*8 + (lane & 3)*2)*2;
            *(uint32_t*)(TB + toff(r, cB))   = packbf(acc[mt][nt][0], acc[mt][nt][1]);
            *(uint32_t*)(TB + toff(r+8, cB)) = packbf(acc[mt][nt][2], acc[mt][nt][3]);
        }
    __syncwarp();

    // GEMM2: z2[v][o] = sum_h tmp[v][h] W2[h][o]  (A rows warp-local)
    #pragma unroll
    for (int m = 0; m < 2; m++)
        #pragma unroll
        for (int n = 0; n < 8; n++) { acc[m][n][0]=0; acc[m][n][1]=0; acc[m][n][2]=0; acc[m][n][3]=0; }
    #pragma unroll
    for (int kt = 0; kt < 4; kt++) {
        uint32_t aH[2][4];
        lda(aH[0], TB, 2*ph,   kt, lane);
        lda(aH[1], TB, 2*ph+1, kt, lane);
        #pragma unroll
        for (int ntp = 0; ntp < 4; ntp++) {
            uint32_t bq[4];
            ldb4(bq, WH, kt, ntp, lane);
            #pragma unroll
            for (int mt = 0; mt < 2; mt++) {
                mmabf(acc[mt][2*ntp],   aH[mt], bq[0], bq[1]);
                mmabf(acc[mt][2*ntp+1], aH[mt], bq[2], bq[3]);
            }
        }
    }
    __syncwarp();
    epi_half(acc, TB, ph, lane, g_z2b + (size_t)bt*4096, g_psum2, g_psq2, bt);
}

// ---------------- K4: S = sum_t [relu(BN1(z1)) + relu(BN2(z2))]; edges ---------
__global__ void __launch_bounds__(256) k_sumfinal() {
    int bv = blockIdx.x, b = bv >> 6, v = bv & 63;
    int tid = threadIdx.x;
    int hq = (tid & 15) << 2, ph = tid >> 4;
    float4 A1 = *(float4*)&g_a1[hq], C1 = *(float4*)&g_c1[hq];
    float4 A2 = *(float4*)&g_a2[hq], C2 = *(float4*)&g_c2[hq];
    float4 s = make_float4(0.f,0.f,0.f,0.f);
    float4 e0 = s, e1 = s;
    #pragma unroll 4
    for (int t = ph; t < TT; t += 16) {
        size_t i1 = (((size_t)(b*TT + t))*64 + v)*64 + hq;
        uint2 u1 = *(const uint2*)&g_z1b[i1];
        uint2 u2 = *(const uint2*)&g_z2b[i1];
        float x0 = fmaxf(fmaf(__uint_as_float(u1.x << 16),         A1.x, C1.x), 0.f)
                 + fmaxf(fmaf(__uint_as_float(u2.x << 16),         A2.x, C2.x), 0.f);
        float x1 = fmaxf(fmaf(__uint_as_float(u1.x & 0xffff0000u), A1.y, C1.y), 0.f)
                 + fmaxf(fmaf(__uint_as_float(u2.x & 0xffff0000u), A2.y, C2.y), 0.f);
        float x2 = fmaxf(fmaf(__uint_as_float(u1.y << 16),         A1.z, C1.z), 0.f)
                 + fmaxf(fmaf(__uint_as_float(u2.y << 16),         A2.z, C2.z), 0.f);
        float x3 = fmaxf(fmaf(__uint_as_float(u1.y & 0xffff0000u), A1.w, C1.w), 0.f)
                 + fmaxf(fmaf(__uint_as_float(u2.y & 0xffff0000u), A2.w, C2.w), 0.f);
        s.x += x0; s.y += x1; s.z += x2; s.w += x3;
        if (t == 0)    e0 = make_float4(x0, x1, x2, x3);
        if (t == TT-1) e1 = make_float4(x0, x1, x2, x3);
    }
    __shared__ float sr[16][64], se0[64], se1[64];
    *(float4*)&sr[ph][hq] = s;
    if (ph == 0)  *(float4*)&se0[hq] = e0;
    if (ph == 15) *(float4*)&se1[hq] = e1;
    __syncthreads();
    if (tid < 64) {
        float S = 0.f;
        #pragma unroll
        for (int p = 0; p < 16; p++) S += sr[p][tid];
        int o = b*4096 + v*64 + tid;
        g_S[o]  = S;
        g_E0[o] = se0[tid];
        g_E1[o] = se1[tid];
    }
}

// ---------------- K5a: pool partials (i-tiles x o-tiles) ----------------------
__global__ void __launch_bounds__(256) k_poolA(const float* __restrict__ tw) {
    int itile = blockIdx.x;   // 0..31
    int otile = blockIdx.y;   // 0..15
    int tid = threadIdx.x, lane = tid & 31, wq = tid >> 5;
    __shared__ float sS[16][128], sE0[16][128], sE1[16][128];
    int i0 = itile*128;
    #pragma unroll
    for (int k = 0; k < 2; k++) {
        int i4 = k*256 + tid;
        int b = i4 >> 5, ii = (i4 & 31) << 2;
        *(float4*)&sS[b][ii]  = *(const float4*)&g_S [b*4096 + i0 + ii];
        *(float4*)&sE0[b][ii] = *(const float4*)&g_E0[b*4096 + i0 + ii];
        *(float4*)&sE1[b][ii] = *(const float4*)&g_E1[b*4096 + i0 + ii];
    }
    __syncthreads();
    #pragma unroll
    for (int pass = 0; pass < 2; pass++) {
        int o = otile*16 + pass*8 + wq;
        float acc[16];
        #pragma unroll
        for (int b = 0; b < 16; b++) acc[b] = 0.f;
        #pragma unroll
        for (int k = 0; k < 4; k++) {
            int i = k*32 + lane;
            const float* twp = tw + ((size_t)o*4096 + i0 + i)*3;
            float t0 = twp[0], t1 = twp[1], t2 = twp[2];
            float ts = t0 + t1 + t2;
            #pragma unroll
            for (int b = 0; b < 16; b++)
                acc[b] += ts*sS[b][i] - t0*sE1[b][i] - t2*sE0[b][i];
        }
        float mine = 0.f;
        #pragma unroll
        for (int b = 0; b < 16; b++) {
            float v = acc[b];
            #pragma unroll
            for (int d = 16; d > 0; d >>= 1) v += __shfl_xor_sync(0xffffffffu, v, d);
            if (lane == b) mine = v;
        }
        if (lane < 16) g_yp[((size_t)itile*256 + o)*16 + lane] = mine;
    }
}

// ---------------- K5b: reduce pool partials ------------------------------------
__global__ void __launch_bounds__(256) k_poolB(const float* __restrict__ tb) {
    int tid = threadIdx.x;
    int o = blockIdx.x*16 + (tid >> 4);
    int b = tid & 15;
    float s = 0.f;
    #pragma unroll 8
    for (int it = 0; it < 32; it++) s += g_yp[((size_t)it*256 + o)*16 + b];
    g_y[b*TC + o] = s*(1.f/TT) + tb[o];
}

// ---------------- K6: FC head ---------------------------------------------------
__global__ void __launch_bounds__(256) k_fc(const float* __restrict__ f1w,
                                            const float* __restrict__ f1b,
                                            const float* __restrict__ f2w,
                                            const float* __restrict__ f2b,
                                            float* __restrict__ out) {
    __shared__ float ys[BB*TC];
    __shared__ float hs[BB*128];
    int tid = threadIdx.x;
    for (int i = tid; i < BB*TC; i += 256) ys[i] = g_y[i];
    __syncthreads();
    int b = tid >> 4, jq = (tid & 15) * 8;
    float acc[8];
    #pragma unroll
    for (int j = 0; j < 8; j++) acc[j] = f1b[jq+j];
    for (int o = 0; o < TC; o++) {
        float yv = ys[b*TC + o];
        const float* w = f1w + o*128 + jq;
        #pragma unroll
        for (int j = 0; j < 8; j++) acc[j] += yv * w[j];
    }
    #pragma unroll
    for (int j = 0; j < 8; j++) hs[b*128 + jq + j] = fmaxf(acc[j], 0.f);
    __syncthreads();
    if (tid < BB*10) {
        int bb = tid / 10, n = tid % 10;
        float s = f2b[n];
        #pragma unroll 8
        for (int j = 0; j < 128; j++) s += hs[bb*128 + j] * f2w[j*10 + n];
        out[tid] = s;
    }
}

// ---------------- launch ---------------------------------------------------------
extern "C" void kernel_launch(void* const* d_in, const int* in_sizes, int n_in,
                              void* d_out, int out_size) {
    const float* x    = (const float*)d_in[0];
    const float* adj  = (const float*)d_in[1];
    const float* w1   = (const float*)d_in[2];
    const float* g1   = (const float*)d_in[4];
    const float* be1  = (const float*)d_in[5];
    const float* w2   = (const float*)d_in[6];
    const float* g2   = (const float*)d_in[8];
    const float* be2  = (const float*)d_in[9];
    const float* tw   = (const float*)d_in[10];
    const float* tb   = (const float*)d_in[11];
    const float* f1w  = (const float*)d_in[12];
    const float* f1b  = (const float*)d_in[13];
    const float* f2w  = (const float*)d_in[14];
    const float* f2b  = (const float*)d_in[15];
    float* out = (float*)d_out;

    cudaFuncSetAttribute(k_l1, cudaFuncAttributeMaxDynamicSharedMemorySize, L1_SM);
    cudaFuncSetAttribute(k_l2, cudaFuncAttributeMaxDynamicSharedMemorySize, L2_SM);

    k_prep<<<BB, 256>>>(adj, w1, w2);
    k_l1<<<BB*128, 128, L1_SM>>>(x);
    k_stats<<<HH, 256>>>(0, g1, be1);
    k_l2<<<BB*128, 256, L2_SM>>>();
    k_stats<<<HH, 256>>>(1, g2, be2);
    k_sumfinal<<<BB*VV, 256>>>();
    dim3 gp(32, 16);
    k_poolA<<<gp, 256>>>(tw);
    k_poolB<<<16, 256>>>(tb);
    k_fc<<<1, 256>>>(f1w, f1b, f2w, f2b, out);
}